// round 6
// baseline (speedup 1.0000x reference)
#include <cuda_runtime.h>
#include <cuda_bf16.h>
#include <cstdint>

// y[n,k] = log( sum_l clip(mu[n,l],EPS) * softmax(leaf_scores[l,:])[k] )
// N=32768, L=256, C=64.
// S = mu_hat @ Q via mma.sync m16n8k16 bf16 hi/lo split (Ah@Bh + Ah@Bl + Al@Bh).
// k-fragment positions remapped so A loads are LDG.128 and each B fragment
// (hi+lo) is a single conflict-free LDS.128. A pipelined at distance 3.

#define LL 256
#define CC 64
#define EPSV 1e-12f
#define TPB 256
#define BN  128
#define BROW 1088   // bytes per B class-row: 256 leaves * (hi+lo) * 2B + 64 pad
                    // (stride % 128 == 64 -> LDS.128 bank-clean per 8-lane phase)

// B: per class row, per 4-leaf group j: [hi x4 bf16][lo x4 bf16] at byte j*16.
__device__ __align__(16) char g_B[CC * BROW];

// ---------------- Kernel 1: softmax + bf16 hi/lo split ----------------
__global__ void softmax_kernel(const float* __restrict__ s) {
    const int l = blockIdx.x;
    const int t = threadIdx.x;
    const float a = s[l * CC + t];
    const float b = s[l * CC + t + 32];
    float m = fmaxf(a, b);
    #pragma unroll
    for (int off = 16; off > 0; off >>= 1)
        m = fmaxf(m, __shfl_xor_sync(0xFFFFFFFFu, m, off));
    const float ea = expf(a - m);
    const float eb = expf(b - m);
    float sum = ea + eb;
    #pragma unroll
    for (int off = 16; off > 0; off >>= 1)
        sum += __shfl_xor_sync(0xFFFFFFFFu, sum, off);
    const float inv = 1.0f / sum;
    const float qa = ea * inv;
    const float qb = eb * inv;

    const int grp = (l >> 2) * 16 + (l & 3) * 2;  // byte offset of hi slot in row
    const __nv_bfloat16 ha = __float2bfloat16(qa);
    const __nv_bfloat16 hb = __float2bfloat16(qb);
    *(__nv_bfloat16*)(g_B + t * BROW + grp)            = ha;
    *(__nv_bfloat16*)(g_B + t * BROW + grp + 8)        =
        __float2bfloat16(qa - __bfloat162float(ha));
    *(__nv_bfloat16*)(g_B + (t + 32) * BROW + grp)     = hb;
    *(__nv_bfloat16*)(g_B + (t + 32) * BROW + grp + 8) =
        __float2bfloat16(qb - __bfloat162float(hb));
}

// ---------------- helpers ----------------
__device__ __forceinline__ void mma_bf16(float* d,
    uint32_t a0, uint32_t a1, uint32_t a2, uint32_t a3, uint32_t b0, uint32_t b1)
{
    asm volatile("mma.sync.aligned.m16n8k16.row.col.f32.bf16.bf16.f32 "
                 "{%0,%1,%2,%3}, {%4,%5,%6,%7}, {%8,%9}, {%0,%1,%2,%3};"
                 : "+f"(d[0]), "+f"(d[1]), "+f"(d[2]), "+f"(d[3])
                 : "r"(a0), "r"(a1), "r"(a2), "r"(a3), "r"(b0), "r"(b1));
}

// split float4 -> hi bf16x2 pairs (e0,e1)(e2,e3) and lo residual pairs
__device__ __forceinline__ void split4(float4 f, uint32_t& h01, uint32_t& h23,
                                       uint32_t& l01, uint32_t& l23) {
    f.x = fmaxf(f.x, EPSV); f.y = fmaxf(f.y, EPSV);
    f.z = fmaxf(f.z, EPSV); f.w = fmaxf(f.w, EPSV);
    __nv_bfloat162 h0 = __float22bfloat162_rn(make_float2(f.x, f.y));
    __nv_bfloat162 h1 = __float22bfloat162_rn(make_float2(f.z, f.w));
    float2 hf0 = __bfloat1622float2(h0);
    float2 hf1 = __bfloat1622float2(h1);
    __nv_bfloat162 l0 = __float22bfloat162_rn(make_float2(f.x - hf0.x, f.y - hf0.y));
    __nv_bfloat162 l1 = __float22bfloat162_rn(make_float2(f.z - hf1.x, f.w - hf1.y));
    h01 = *reinterpret_cast<uint32_t*>(&h0);
    h23 = *reinterpret_cast<uint32_t*>(&h1);
    l01 = *reinterpret_cast<uint32_t*>(&l0);
    l23 = *reinterpret_cast<uint32_t*>(&l1);
}

// ---------------- Kernel 2: HMMA mixture GEMM + log ----------------
extern __shared__ char sB[];   // [CC * BROW] = 69632 bytes

__global__ void __launch_bounds__(TPB, 2) leafmix_kernel(
    const float* __restrict__ mu, float* __restrict__ out)
{
    // stage B into smem, coalesced uint4: 4352 / 256 = 17 iters exact
    {
        const uint4* gq = (const uint4*)g_B;
        uint4* sq = (uint4*)sB;
        #pragma unroll
        for (int j = 0; j < 17; j++)
            sq[threadIdx.x + j * TPB] = gq[threadIdx.x + j * TPB];
    }
    __syncthreads();

    const int tid = threadIdx.x;
    const int w = tid >> 5;
    const int lane = tid & 31;
    const int g = lane >> 2;   // row-group / B-column index
    const int r = lane & 3;    // k quad

    const int row0 = blockIdx.x * BN + w * 16 + g;
    const float* A0 = mu + (size_t)row0 * LL + r * 4;
    const float* A1 = A0 + 8 * LL;

    const char* Bp = sB + g * BROW + r * 16;   // lane's fragment column in B

    float acc[8][4];
    #pragma unroll
    for (int nt = 0; nt < 8; nt++)
        #pragma unroll
        for (int q = 0; q < 4; q++) acc[nt][q] = 0.0f;

    // ---- A register ring, prefetch distance 3 ----
    float4 fa[4], fb[4];
    #pragma unroll
    for (int p = 0; p < 3; p++) {
        fa[p] = *(const float4*)(A0 + p * 16);
        fb[p] = *(const float4*)(A1 + p * 16);
    }

    #pragma unroll
    for (int kk = 0; kk < 16; kk++) {
        if (kk + 3 < 16) {
            fa[(kk + 3) & 3] = *(const float4*)(A0 + (kk + 3) * 16);
            fb[(kk + 3) & 3] = *(const float4*)(A1 + (kk + 3) * 16);
        }

        uint32_t ah0, ah2, al0, al2;   // row g:   (e0,e1),(e2,e3)
        uint32_t ah1, ah3, al1, al3;   // row g+8
        split4(fa[kk & 3], ah0, ah2, al0, al2);
        split4(fb[kk & 3], ah1, ah3, al1, al3);

        const char* bk = Bp + kk * 64;
        #pragma unroll
        for (int nt = 0; nt < 8; nt++) {
            const uint4 q = *(const uint4*)(bk + nt * 8 * BROW);
            mma_bf16(acc[nt], ah0, ah1, ah2, ah3, q.x, q.y);
            mma_bf16(acc[nt], ah0, ah1, ah2, ah3, q.z, q.w);
            mma_bf16(acc[nt], al0, al1, al2, al3, q.x, q.y);
        }
    }

    // ---- epilogue: log + store ----
    float* o0 = out + (size_t)row0 * CC + r * 2;
    float* o1 = o0 + 8 * CC;
    #pragma unroll
    for (int nt = 0; nt < 8; nt++) {
        *(float2*)(o0 + nt * 8) = make_float2(__logf(acc[nt][0]), __logf(acc[nt][1]));
        *(float2*)(o1 + nt * 8) = make_float2(__logf(acc[nt][2]), __logf(acc[nt][3]));
    }
}

extern "C" void kernel_launch(void* const* d_in, const int* in_sizes, int n_in,
                              void* d_out, int out_size) {
    const float* mu = (const float*)d_in[0];           // (N, L) fp32
    const float* leaf_scores = (const float*)d_in[1];  // (L, C) fp32
    float* out = (float*)d_out;                        // (N, C) fp32

    const int N = in_sizes[0] / LL;
    const int smem_bytes = CC * BROW;   // 69632

    static bool attr_set = false;
    if (!attr_set) {
        cudaFuncSetAttribute(leafmix_kernel,
                             cudaFuncAttributeMaxDynamicSharedMemorySize, smem_bytes);
        attr_set = true;
    }

    softmax_kernel<<<LL, 32>>>(leaf_scores);
    leafmix_kernel<<<N / BN, TPB, smem_bytes>>>(mu, out);
}

// round 7
// speedup vs baseline: 1.0084x; 1.0084x over previous
#include <cuda_runtime.h>
#include <cuda_bf16.h>
#include <cstdint>

// y[n,k] = log( sum_l clip(mu[n,l],EPS) * softmax(leaf_scores[l,:])[k] )
// N=32768, L=256, C=64.
// S = mu_hat @ Q via mma.sync m16n8k16 bf16 hi/lo split (Ah@Bh + Ah@Bl + Al@Bh).
// Warp computes m=32 (two m16 tiles stacked) x n=64: every B fragment (one
// LDS.128) feeds 6 MMAs. A loaded as LDG.128 with a 2-deep register ring.

#define LL 256
#define CC 64
#define EPSV 1e-12f
#define TPB 128
#define BN  128
#define BROW 1088   // bytes per B class-row: 256*(hi+lo)*2B + 64 pad (bank-clean)

// B: per class row, per 4-leaf group j: [hi x4 bf16][lo x4 bf16] at byte j*16.
__device__ __align__(16) char g_B[CC * BROW];

// ---------------- Kernel 1: softmax + bf16 hi/lo split ----------------
__global__ void softmax_kernel(const float* __restrict__ s) {
    const int l = blockIdx.x;
    const int t = threadIdx.x;
    const float a = s[l * CC + t];
    const float b = s[l * CC + t + 32];
    float m = fmaxf(a, b);
    #pragma unroll
    for (int off = 16; off > 0; off >>= 1)
        m = fmaxf(m, __shfl_xor_sync(0xFFFFFFFFu, m, off));
    const float ea = expf(a - m);
    const float eb = expf(b - m);
    float sum = ea + eb;
    #pragma unroll
    for (int off = 16; off > 0; off >>= 1)
        sum += __shfl_xor_sync(0xFFFFFFFFu, sum, off);
    const float inv = 1.0f / sum;
    const float qa = ea * inv;
    const float qb = eb * inv;

    const int grp = (l >> 2) * 16 + (l & 3) * 2;
    const __nv_bfloat16 ha = __float2bfloat16(qa);
    const __nv_bfloat16 hb = __float2bfloat16(qb);
    *(__nv_bfloat16*)(g_B + t * BROW + grp)            = ha;
    *(__nv_bfloat16*)(g_B + t * BROW + grp + 8)        =
        __float2bfloat16(qa - __bfloat162float(ha));
    *(__nv_bfloat16*)(g_B + (t + 32) * BROW + grp)     = hb;
    *(__nv_bfloat16*)(g_B + (t + 32) * BROW + grp + 8) =
        __float2bfloat16(qb - __bfloat162float(hb));
}

// ---------------- helpers ----------------
__device__ __forceinline__ void mma_bf16(float* d,
    uint32_t a0, uint32_t a1, uint32_t a2, uint32_t a3, uint32_t b0, uint32_t b1)
{
    asm volatile("mma.sync.aligned.m16n8k16.row.col.f32.bf16.bf16.f32 "
                 "{%0,%1,%2,%3}, {%4,%5,%6,%7}, {%8,%9}, {%0,%1,%2,%3};"
                 : "+f"(d[0]), "+f"(d[1]), "+f"(d[2]), "+f"(d[3])
                 : "r"(a0), "r"(a1), "r"(a2), "r"(a3), "r"(b0), "r"(b1));
}

__device__ __forceinline__ void split4(float4 f, uint32_t& h01, uint32_t& h23,
                                       uint32_t& l01, uint32_t& l23) {
    f.x = fmaxf(f.x, EPSV); f.y = fmaxf(f.y, EPSV);
    f.z = fmaxf(f.z, EPSV); f.w = fmaxf(f.w, EPSV);
    __nv_bfloat162 h0 = __float22bfloat162_rn(make_float2(f.x, f.y));
    __nv_bfloat162 h1 = __float22bfloat162_rn(make_float2(f.z, f.w));
    float2 hf0 = __bfloat1622float2(h0);
    float2 hf1 = __bfloat1622float2(h1);
    __nv_bfloat162 l0 = __float22bfloat162_rn(make_float2(f.x - hf0.x, f.y - hf0.y));
    __nv_bfloat162 l1 = __float22bfloat162_rn(make_float2(f.z - hf1.x, f.w - hf1.y));
    h01 = *reinterpret_cast<uint32_t*>(&h0);
    h23 = *reinterpret_cast<uint32_t*>(&h1);
    l01 = *reinterpret_cast<uint32_t*>(&l0);
    l23 = *reinterpret_cast<uint32_t*>(&l1);
}

// ---------------- Kernel 2: HMMA mixture GEMM + log ----------------
extern __shared__ char sB[];   // [CC * BROW] = 69632 bytes

__global__ void __launch_bounds__(TPB, 3) leafmix_kernel(
    const float* __restrict__ mu, float* __restrict__ out)
{
    // stage B into smem, coalesced uint4: 4352 / 128 = 34 iters exact
    {
        const uint4* gq = (const uint4*)g_B;
        uint4* sq = (uint4*)sB;
        #pragma unroll
        for (int j = 0; j < 34; j++)
            sq[threadIdx.x + j * TPB] = gq[threadIdx.x + j * TPB];
    }
    __syncthreads();

    const int tid = threadIdx.x;
    const int w = tid >> 5;
    const int lane = tid & 31;
    const int g = lane >> 2;   // row-group / B-column index
    const int r = lane & 3;    // k quad

    const int rb = blockIdx.x * BN + w * 32 + g;
    const float* A0 = mu + (size_t)rb * LL + r * 4;   // row g
    const float* A1 = A0 + 8 * LL;                    // row g+8
    const float* A2 = A0 + 16 * LL;                   // row g+16
    const float* A3 = A0 + 24 * LL;                   // row g+24

    const char* Bp = sB + g * BROW + r * 16;

    float acc0[8][4], acc1[8][4];
    #pragma unroll
    for (int nt = 0; nt < 8; nt++)
        #pragma unroll
        for (int q = 0; q < 4; q++) { acc0[nt][q] = 0.0f; acc1[nt][q] = 0.0f; }

    // ---- A register ring, prefetch distance 2, 4 rows ----
    float4 ra[2][4];
    #pragma unroll
    for (int p = 0; p < 2; p++) {
        ra[p][0] = *(const float4*)(A0 + p * 16);
        ra[p][1] = *(const float4*)(A1 + p * 16);
        ra[p][2] = *(const float4*)(A2 + p * 16);
        ra[p][3] = *(const float4*)(A3 + p * 16);
    }

    #pragma unroll
    for (int kk = 0; kk < 16; kk++) {
        const int p = kk & 1;

        uint32_t ah0, ah2, al0, al2;   // row g
        uint32_t ah1, ah3, al1, al3;   // row g+8
        uint32_t ch0, ch2, cl0, cl2;   // row g+16
        uint32_t ch1, ch3, cl1, cl3;   // row g+24
        split4(ra[p][0], ah0, ah2, al0, al2);
        split4(ra[p][1], ah1, ah3, al1, al3);
        split4(ra[p][2], ch0, ch2, cl0, cl2);
        split4(ra[p][3], ch1, ch3, cl1, cl3);

        if (kk + 2 < 16) {
            ra[p][0] = *(const float4*)(A0 + (kk + 2) * 16);
            ra[p][1] = *(const float4*)(A1 + (kk + 2) * 16);
            ra[p][2] = *(const float4*)(A2 + (kk + 2) * 16);
            ra[p][3] = *(const float4*)(A3 + (kk + 2) * 16);
        }

        const char* bk = Bp + kk * 64;
        #pragma unroll
        for (int nt = 0; nt < 8; nt++) {
            const uint4 q = *(const uint4*)(bk + nt * 8 * BROW);
            mma_bf16(acc0[nt], ah0, ah1, ah2, ah3, q.x, q.y);
            mma_bf16(acc0[nt], ah0, ah1, ah2, ah3, q.z, q.w);
            mma_bf16(acc0[nt], al0, al1, al2, al3, q.x, q.y);
            mma_bf16(acc1[nt], ch0, ch1, ch2, ch3, q.x, q.y);
            mma_bf16(acc1[nt], ch0, ch1, ch2, ch3, q.z, q.w);
            mma_bf16(acc1[nt], cl0, cl1, cl2, cl3, q.x, q.y);
        }
    }

    // ---- epilogue: log + store ----
    float* o0 = out + (size_t)rb * CC + r * 2;
    float* o1 = o0 + 8 * CC;
    float* o2 = o0 + 16 * CC;
    float* o3 = o0 + 24 * CC;
    #pragma unroll
    for (int nt = 0; nt < 8; nt++) {
        *(float2*)(o0 + nt * 8) = make_float2(__logf(acc0[nt][0]), __logf(acc0[nt][1]));
        *(float2*)(o1 + nt * 8) = make_float2(__logf(acc0[nt][2]), __logf(acc0[nt][3]));
        *(float2*)(o2 + nt * 8) = make_float2(__logf(acc1[nt][0]), __logf(acc1[nt][1]));
        *(float2*)(o3 + nt * 8) = make_float2(__logf(acc1[nt][2]), __logf(acc1[nt][3]));
    }
}

extern "C" void kernel_launch(void* const* d_in, const int* in_sizes, int n_in,
                              void* d_out, int out_size) {
    const float* mu = (const float*)d_in[0];           // (N, L) fp32
    const float* leaf_scores = (const float*)d_in[1];  // (L, C) fp32
    float* out = (float*)d_out;                        // (N, C) fp32

    const int N = in_sizes[0] / LL;
    const int smem_bytes = CC * BROW;   // 69632

    static bool attr_set = false;
    if (!attr_set) {
        cudaFuncSetAttribute(leafmix_kernel,
                             cudaFuncAttributeMaxDynamicSharedMemorySize, smem_bytes);
        attr_set = true;
    }

    softmax_kernel<<<LL, 32>>>(leaf_scores);
    leafmix_kernel<<<N / BN, TPB, smem_bytes>>>(mu, out);
}

// round 9
// speedup vs baseline: 1.2888x; 1.2780x over previous
#include <cuda_runtime.h>
#include <cuda_fp16.h>
#include <cstdint>

// y[n,k] = log( sum_l clip(mu[n,l],EPS) * softmax(leaf_scores[l,:])[k] )
// N=32768, L=256, C=64.
// S = mu_hat @ Q via mma.sync m16n8k16 fp16, 2-pass split:
//   S ~= Ah@B + Al@B   (A = fp16 hi + fp16 residual, B = fp16 single)
// Error bound: |dS| <= 2^-12 * S (B rounding)  ->  norm rel_err ~1e-4 << 1e-3.
// BN=64, TPB=128, grid=512 -> 3-4 CTAs/SM resident; B smem 34.8 KB.

#define LL 256
#define CC 64
#define EPSV 1e-12f
#define TPB 128
#define BN  64
#define BROWH 544   // bytes per B class-row: 256 fp16 (512B) + 32 pad
                    // (stride%128==32 -> each 16-lane LDS.64 phase bank-clean)

// B: per class row, leaf group j (4 leaves) at byte j*8: [hi x4 fp16].
__device__ __align__(16) char g_B[CC * BROWH];

// ---------------- Kernel 1: softmax -> fp16 Q ----------------
__global__ void softmax_kernel(const float* __restrict__ s) {
    const int l = blockIdx.x;
    const int t = threadIdx.x;
    const float a = s[l * CC + t];
    const float b = s[l * CC + t + 32];
    float m = fmaxf(a, b);
    #pragma unroll
    for (int off = 16; off > 0; off >>= 1)
        m = fmaxf(m, __shfl_xor_sync(0xFFFFFFFFu, m, off));
    const float ea = expf(a - m);
    const float eb = expf(b - m);
    float sum = ea + eb;
    #pragma unroll
    for (int off = 16; off > 0; off >>= 1)
        sum += __shfl_xor_sync(0xFFFFFFFFu, sum, off);
    const float inv = 1.0f / sum;

    const int grp = (l >> 2) * 8 + (l & 3) * 2;   // byte offset within class row
    *(__half*)(g_B + t * BROWH + grp)        = __float2half_rn(ea * inv);
    *(__half*)(g_B + (t + 32) * BROWH + grp) = __float2half_rn(eb * inv);
}

// ---------------- helpers ----------------
__device__ __forceinline__ void mma_f16(float* d,
    uint32_t a0, uint32_t a1, uint32_t a2, uint32_t a3, uint32_t b0, uint32_t b1)
{
    asm volatile("mma.sync.aligned.m16n8k16.row.col.f32.f16.f16.f32 "
                 "{%0,%1,%2,%3}, {%4,%5,%6,%7}, {%8,%9}, {%0,%1,%2,%3};"
                 : "+f"(d[0]), "+f"(d[1]), "+f"(d[2]), "+f"(d[3])
                 : "r"(a0), "r"(a1), "r"(a2), "r"(a3), "r"(b0), "r"(b1));
}

// split float4 -> fp16 hi pairs (e0,e1)(e2,e3) and fp16 residual pairs
__device__ __forceinline__ void split4(float4 f, uint32_t& h01, uint32_t& h23,
                                       uint32_t& l01, uint32_t& l23) {
    f.x = fmaxf(f.x, EPSV); f.y = fmaxf(f.y, EPSV);
    f.z = fmaxf(f.z, EPSV); f.w = fmaxf(f.w, EPSV);
    __half2 h0 = __float22half2_rn(make_float2(f.x, f.y));
    __half2 h1 = __float22half2_rn(make_float2(f.z, f.w));
    float2 hf0 = __half22float2(h0);
    float2 hf1 = __half22float2(h1);
    __half2 l0 = __float22half2_rn(make_float2(f.x - hf0.x, f.y - hf0.y));
    __half2 l1 = __float22half2_rn(make_float2(f.z - hf1.x, f.w - hf1.y));
    h01 = *reinterpret_cast<uint32_t*>(&h0);
    h23 = *reinterpret_cast<uint32_t*>(&h1);
    l01 = *reinterpret_cast<uint32_t*>(&l0);
    l23 = *reinterpret_cast<uint32_t*>(&l1);
}

// ---------------- Kernel 2: HMMA mixture GEMM + log ----------------
extern __shared__ char sB[];   // [CC * BROWH] = 34816 bytes

__global__ void __launch_bounds__(TPB, 4) leafmix_kernel(
    const float* __restrict__ mu, float* __restrict__ out)
{
    // stage B into smem, coalesced uint4: 2176 / 128 = 17 iters exact
    {
        const uint4* gq = (const uint4*)g_B;
        uint4* sq = (uint4*)sB;
        #pragma unroll
        for (int j = 0; j < 17; j++)
            sq[threadIdx.x + j * TPB] = gq[threadIdx.x + j * TPB];
    }
    __syncthreads();

    const int tid = threadIdx.x;
    const int w = tid >> 5;
    const int lane = tid & 31;
    const int g = lane >> 2;   // row-group / B-column index
    const int r = lane & 3;    // k quad

    const int rb = blockIdx.x * BN + w * 16 + g;
    const float* A0 = mu + (size_t)rb * LL + r * 4;   // row g
    const float* A1 = A0 + 8 * LL;                    // row g+8

    const char* Bp = sB + g * BROWH + r * 8;

    float acc[8][4];
    #pragma unroll
    for (int nt = 0; nt < 8; nt++)
        #pragma unroll
        for (int q = 0; q < 4; q++) acc[nt][q] = 0.0f;

    // ---- A register ring, prefetch distance 2 ----
    float4 fa[2], fb[2];
    #pragma unroll
    for (int p = 0; p < 2; p++) {
        fa[p] = *(const float4*)(A0 + p * 16);
        fb[p] = *(const float4*)(A1 + p * 16);
    }

    #pragma unroll
    for (int kk = 0; kk < 16; kk++) {
        const int p = kk & 1;

        uint32_t ah0, ah2, al0, al2;   // row g:   (e0,e1),(e2,e3)
        uint32_t ah1, ah3, al1, al3;   // row g+8
        split4(fa[p], ah0, ah2, al0, al2);
        split4(fb[p], ah1, ah3, al1, al3);

        if (kk + 2 < 16) {
            fa[p] = *(const float4*)(A0 + (kk + 2) * 16);
            fb[p] = *(const float4*)(A1 + (kk + 2) * 16);
        }

        const char* bk = Bp + kk * 32;
        #pragma unroll
        for (int nt = 0; nt < 8; nt++) {
            const uint2 q = *(const uint2*)(bk + nt * 8 * BROWH);
            mma_f16(acc[nt], ah0, ah1, ah2, ah3, q.x, q.y);
            mma_f16(acc[nt], al0, al1, al2, al3, q.x, q.y);
        }
    }

    // ---- epilogue: log + store ----
    float* o0 = out + (size_t)rb * CC + r * 2;
    float* o1 = o0 + 8 * CC;
    #pragma unroll
    for (int nt = 0; nt < 8; nt++) {
        *(float2*)(o0 + nt * 8) = make_float2(__logf(acc[nt][0]), __logf(acc[nt][1]));
        *(float2*)(o1 + nt * 8) = make_float2(__logf(acc[nt][2]), __logf(acc[nt][3]));
    }
}

extern "C" void kernel_launch(void* const* d_in, const int* in_sizes, int n_in,
                              void* d_out, int out_size) {
    const float* mu = (const float*)d_in[0];           // (N, L) fp32
    const float* leaf_scores = (const float*)d_in[1];  // (L, C) fp32
    float* out = (float*)d_out;                        // (N, C) fp32

    const int N = in_sizes[0] / LL;
    const int smem_bytes = CC * BROWH;   // 34816

    static bool attr_set = false;
    if (!attr_set) {
        cudaFuncSetAttribute(leafmix_kernel,
                             cudaFuncAttributeMaxDynamicSharedMemorySize, smem_bytes);
        attr_set = true;
    }

    softmax_kernel<<<LL, 32>>>(leaf_scores);
    leafmix_kernel<<<N / BN, TPB, smem_bytes>>>(mu, out);
}